// round 10
// baseline (speedup 1.0000x reference)
#include <cuda_runtime.h>
#include <cuda_bf16.h>
#include <math.h>
#include <stdint.h>

#define B_    16384
#define D_    2048
#define F1_   32
#define N1_   33
#define N2_   1056       // F1*(F2+1)
#define NCAT_ 1089       // N2_ + N1_
#define NPAD_ 1152       // padded to 9*128
#define NOUT_ 1024

// ---------------- scratch (device globals; allocation-free) ----------------
__device__ __nv_bfloat16 g_xhi[(size_t)B_ * D_];
__device__ __nv_bfloat16 g_xlo[(size_t)B_ * D_];
__device__ __nv_bfloat16 g_whi[(size_t)NPAD_ * D_];
__device__ __nv_bfloat16 g_wlo[(size_t)NPAD_ * D_];
__device__ float g_bias[NPAD_];
__device__ float g_col0[(size_t)B_ * F1_];   // logits2[:, :, 0]
__device__ float g_l1[(size_t)B_ * N1_];
__device__ float g_ce1p[B_];
__device__ float g_ce2p[B_];

// ---------------- PTX helpers (sm_80+ only) ----------------
__device__ __forceinline__ uint32_t smem_u32(const void* p) {
    uint32_t a;
    asm("{ .reg .u64 t; cvta.to.shared.u64 t, %1; cvt.u32.u64 %0, t; }"
        : "=r"(a) : "l"(p));
    return a;
}
__device__ __forceinline__ void cpasync16(uint32_t dst, const void* src) {
    asm volatile("cp.async.cg.shared.global [%0], [%1], 16;"
                 :: "r"(dst), "l"(src) : "memory");
}
#define CP_COMMIT() asm volatile("cp.async.commit_group;" ::: "memory")

#define SW128(o) ((o) ^ (((o) >> 3) & 0x70))

__device__ __forceinline__ void ldsm_x4(uint32_t* r, uint32_t addr) {
    asm volatile("ldmatrix.sync.aligned.m8n8.x4.shared.b16 {%0,%1,%2,%3}, [%4];"
                 : "=r"(r[0]), "=r"(r[1]), "=r"(r[2]), "=r"(r[3]) : "r"(addr));
}
__device__ __forceinline__ void ldsm_x2(uint32_t* r, uint32_t addr) {
    asm volatile("ldmatrix.sync.aligned.m8n8.x2.shared.b16 {%0,%1}, [%2];"
                 : "=r"(r[0]), "=r"(r[1]) : "r"(addr));
}
__device__ __forceinline__ void mma_bf16(float* d, const uint32_t* a, const uint32_t* b) {
    asm volatile(
        "mma.sync.aligned.m16n8k16.row.col.f32.bf16.bf16.f32 "
        "{%0,%1,%2,%3}, {%4,%5,%6,%7}, {%8,%9}, {%0,%1,%2,%3};"
        : "+f"(d[0]), "+f"(d[1]), "+f"(d[2]), "+f"(d[3])
        : "r"(a[0]), "r"(a[1]), "r"(a[2]), "r"(a[3]), "r"(b[0]), "r"(b[1]));
}

// ---------------- conversion kernels ----------------
__global__ __launch_bounds__(256)
void conv_x_k(const float* __restrict__ x)
{
    const size_t n4 = (size_t)B_ * D_ / 4;
    __nv_bfloat162* hi2 = reinterpret_cast<__nv_bfloat162*>(g_xhi);
    __nv_bfloat162* lo2 = reinterpret_cast<__nv_bfloat162*>(g_xlo);
    for (size_t i = (size_t)blockIdx.x * blockDim.x + threadIdx.x; i < n4;
         i += (size_t)gridDim.x * blockDim.x) {
        float4 v = reinterpret_cast<const float4*>(x)[i];
        __nv_bfloat16 h0 = __float2bfloat16(v.x);
        __nv_bfloat16 h1 = __float2bfloat16(v.y);
        __nv_bfloat16 h2 = __float2bfloat16(v.z);
        __nv_bfloat16 h3 = __float2bfloat16(v.w);
        __nv_bfloat16 l0 = __float2bfloat16(v.x - __bfloat162float(h0));
        __nv_bfloat16 l1 = __float2bfloat16(v.y - __bfloat162float(h1));
        __nv_bfloat16 l2 = __float2bfloat16(v.z - __bfloat162float(h2));
        __nv_bfloat16 l3 = __float2bfloat16(v.w - __bfloat162float(h3));
        __nv_bfloat162 a, b, c, d;
        a.x = h0; a.y = h1; b.x = h2; b.y = h3;
        c.x = l0; c.y = l1; d.x = l2; d.y = l3;
        hi2[i * 2] = a; hi2[i * 2 + 1] = b;
        lo2[i * 2] = c; lo2[i * 2 + 1] = d;
    }
}

__global__ __launch_bounds__(256)
void conv_w_k(const float* __restrict__ W2, const float* __restrict__ W1,
              const float* __restrict__ b2, const float* __restrict__ b1)
{
    const size_t n4 = (size_t)NPAD_ * D_ / 4;
    __nv_bfloat162* hi2 = reinterpret_cast<__nv_bfloat162*>(g_whi);
    __nv_bfloat162* lo2 = reinterpret_cast<__nv_bfloat162*>(g_wlo);
    size_t tid0 = (size_t)blockIdx.x * blockDim.x + threadIdx.x;
    for (size_t i = tid0; i < n4; i += (size_t)gridDim.x * blockDim.x) {
        size_t row = i >> 9;
        size_t inr = i & 511;
        float4 v = make_float4(0.f, 0.f, 0.f, 0.f);
        if (row < N2_)
            v = reinterpret_cast<const float4*>(W2)[row * 512 + inr];
        else if (row < NCAT_)
            v = reinterpret_cast<const float4*>(W1)[(row - N2_) * 512 + inr];
        __nv_bfloat16 h0 = __float2bfloat16(v.x);
        __nv_bfloat16 h1 = __float2bfloat16(v.y);
        __nv_bfloat16 h2 = __float2bfloat16(v.z);
        __nv_bfloat16 h3 = __float2bfloat16(v.w);
        __nv_bfloat16 l0 = __float2bfloat16(v.x - __bfloat162float(h0));
        __nv_bfloat16 l1 = __float2bfloat16(v.y - __bfloat162float(h1));
        __nv_bfloat16 l2 = __float2bfloat16(v.z - __bfloat162float(h2));
        __nv_bfloat16 l3 = __float2bfloat16(v.w - __bfloat162float(h3));
        __nv_bfloat162 a, b, c, d;
        a.x = h0; a.y = h1; b.x = h2; b.y = h3;
        c.x = l0; c.y = l1; d.x = l2; d.y = l3;
        hi2[i * 2] = a; hi2[i * 2 + 1] = b;
        lo2[i * 2] = c; lo2[i * 2 + 1] = d;
    }
    if (tid0 < NPAD_) {
        float bv = 0.f;
        if (tid0 < N2_)        bv = b2[tid0];
        else if (tid0 < NCAT_) bv = b1[tid0 - N2_];
        g_bias[tid0] = bv;
    }
}

// ---------------- warp-MMA GEMM + fused scatter epilogue ----------------
// grid (9, 128); BM=BN=128, BK=64; 8 warps, warp tile 64x32.
// 3-stage cp.async pipeline, ONE __syncthreads per K-tile:
//   load(kt+2) writes stage (kt+2)%3 whose last readers were kt-1 —
//   already fenced by this kt's barrier.
#define KTILES 32
#define STAGE_BYTES 65536
#define SMEM_DYN (3 * STAGE_BYTES + 1024)

__global__ __launch_bounds__(256, 1)
void gemm_mma(float* __restrict__ out)
{
    extern __shared__ char dyn[];
    const uint32_t base = (smem_u32(dyn) + 1023u) & ~1023u;

    const int tid = threadIdx.x;
    const int wid = tid >> 5;
    const int lid = tid & 31;
    const int bn = blockIdx.x * 128;
    const int bm = blockIdx.y * 128;

    const int wm = (wid & 1) * 64;
    const int wn = (wid >> 1) * 32;

    float acc[4][4][4];
#pragma unroll
    for (int i = 0; i < 4; i++)
#pragma unroll
        for (int j = 0; j < 4; j++)
#pragma unroll
            for (int k = 0; k < 4; k++) acc[i][j][k] = 0.f;

    auto load_tile = [&](int kt) {
        const uint32_t sb = base + (kt % 3) * STAGE_BYTES;
        const int kelt = kt * 64;
#pragma unroll
        for (int q = 0; q < 4; q++) {
            int id  = q * 256 + tid;
            int row = id >> 3;
            int c   = id & 7;
            uint32_t off = SW128((uint32_t)(row * 128 + c * 16));
            size_t aoff = (size_t)(bm + row) * D_ + kelt + c * 8;
            size_t boff = (size_t)(bn + row) * D_ + kelt + c * 8;
            cpasync16(sb + 0     + off, g_xhi + aoff);
            cpasync16(sb + 16384 + off, g_xlo + aoff);
            cpasync16(sb + 32768 + off, g_whi + boff);
            cpasync16(sb + 49152 + off, g_wlo + boff);
        }
    };

    load_tile(0); CP_COMMIT();
    load_tile(1); CP_COMMIT();

    const int a_r  = ((lid >> 3) & 1) * 8 + (lid & 7);
    const int a_kb = ((lid >> 4) & 1) * 8;
    const int b_r  = lid & 7;
    const int b_kb = ((lid >> 3) & 1) * 8;

    for (int kt = 0; kt < KTILES; kt++) {
        // ensure load(kt) landed (keep the newest group in flight)
        if (kt + 1 < KTILES) asm volatile("cp.async.wait_group 1;" ::: "memory");
        else                 asm volatile("cp.async.wait_group 0;" ::: "memory");
        __syncthreads();   // single barrier per kt: publishes load(kt),
                           // and fences kt-1 readers before stage reuse below

        if (kt + 2 < KTILES) { load_tile(kt + 2); CP_COMMIT(); }

        const uint32_t sb  = base + (kt % 3) * STAGE_BYTES;
        const uint32_t sAh = sb;
        const uint32_t sAl = sb + 16384;
        const uint32_t sBh = sb + 32768;
        const uint32_t sBl = sb + 49152;

#pragma unroll
        for (int k16 = 0; k16 < 4; k16++) {
            const int kb = k16 * 16;
            uint32_t ah[4][4], al[4][4], bh[4][2], bl[4][2];
#pragma unroll
            for (int mf = 0; mf < 4; mf++) {
                uint32_t off = (uint32_t)((wm + mf * 16 + a_r) * 128 + (kb + a_kb) * 2);
                uint32_t sw = SW128(off);
                ldsm_x4(ah[mf], sAh + sw);
                ldsm_x4(al[mf], sAl + sw);
            }
#pragma unroll
            for (int nf = 0; nf < 4; nf++) {
                uint32_t off = (uint32_t)((wn + nf * 8 + b_r) * 128 + (kb + b_kb) * 2);
                uint32_t sw = SW128(off);
                ldsm_x2(bh[nf], sBh + sw);
                ldsm_x2(bl[nf], sBl + sw);
            }
#pragma unroll
            for (int mf = 0; mf < 4; mf++)
#pragma unroll
                for (int nf = 0; nf < 4; nf++)
                    mma_bf16(acc[mf][nf], ah[mf], bh[nf]);
#pragma unroll
            for (int mf = 0; mf < 4; mf++)
#pragma unroll
                for (int nf = 0; nf < 4; nf++)
                    mma_bf16(acc[mf][nf], ah[mf], bl[nf]);
#pragma unroll
            for (int mf = 0; mf < 4; mf++)
#pragma unroll
                for (int nf = 0; nf < 4; nf++)
                    mma_bf16(acc[mf][nf], al[mf], bh[nf]);
        }
        // no second barrier: next kt's barrier fences this kt's readers
    }

    // ---- fused scatter epilogue ----
    const int lrow = lid >> 2;
    const int lcol = (lid & 3) * 2;

#pragma unroll
    for (int mf = 0; mf < 4; mf++)
#pragma unroll
        for (int nf = 0; nf < 4; nf++) {
            int r0 = bm + wm + mf * 16 + lrow;
            int c0 = bn + wn + nf * 8 + lcol;
            float* d = acc[mf][nf];
#pragma unroll
            for (int e = 0; e < 4; e++) {
                int rr = r0 + (e >> 1) * 8;
                int cc = c0 + (e & 1);
                float v = d[e] + g_bias[cc];
                if (cc < N2_) {
                    int j = cc / 33;
                    int k = cc - j * 33;
                    if (k > 0)
                        out[(size_t)rr * NOUT_ + j * 32 + (k - 1)] = v;
                    else
                        g_col0[(size_t)rr * F1_ + j] = v;
                } else if (cc < NCAT_) {
                    g_l1[(size_t)rr * N1_ + (cc - N2_)] = v;
                }
            }
        }
}

// ---------------- warp-per-row CE penalty kernel ----------------
__global__ __launch_bounds__(256)
void penalty_ce(const int* __restrict__ labels, const float* __restrict__ out)
{
    const int wid = threadIdx.x >> 5;
    const int j   = threadIdx.x & 31;
    const int b   = blockIdx.x * 8 + wid;

    const int lab = labels[b];
    const int g = lab >> 5;
    const int w = lab & 31;

    const float* rowp = out + (size_t)b * NOUT_ + j * 32;
    float p[32];
#pragma unroll
    for (int q = 0; q < 8; q++) {
        float4 v = *reinterpret_cast<const float4*>(rowp + q * 4);
        p[q * 4 + 0] = v.x; p[q * 4 + 1] = v.y;
        p[q * 4 + 2] = v.z; p[q * 4 + 3] = v.w;
    }
    float p0 = g_col0[(size_t)b * F1_ + j];

    float m = p0;
#pragma unroll
    for (int k = 0; k < 32; k++) m = fmaxf(m, p[k]);
    float s = expf(p0 - m);
#pragma unroll
    for (int k = 0; k < 32; k++) s += expf(p[k] - m);
    float lse = m + logf(s);
    float tgt = (j == g) ? p[w] : p0;
    float v = lse - tgt;
#pragma unroll
    for (int o = 16; o > 0; o >>= 1)
        v += __shfl_down_sync(0xffffffffu, v, o);

    const float* l1p = g_l1 + (size_t)b * N1_;
    float q1 = l1p[j];
    float q2 = (j == 0) ? l1p[32] : -1e30f;
    float mm = fmaxf(q1, q2);
#pragma unroll
    for (int o = 16; o > 0; o >>= 1)
        mm = fmaxf(mm, __shfl_xor_sync(0xffffffffu, mm, o));
    float ss = expf(q1 - mm) + ((j == 0) ? expf(q2 - mm) : 0.f);
#pragma unroll
    for (int o = 16; o > 0; o >>= 1)
        ss += __shfl_xor_sync(0xffffffffu, ss, o);
    if (j == 0) {
        g_ce2p[b] = v;
        float tgt1 = l1p[g + 1];
        g_ce1p[b] = mm + logf(ss) - tgt1;
    }
}

__global__ __launch_bounds__(256)
void finalize_penalty(float* __restrict__ out, long long pen_idx)
{
    __shared__ float s1[256];
    __shared__ float s2[256];
    float a = 0.f, c = 0.f;
    for (int i = threadIdx.x; i < B_; i += 256) {
        a += g_ce1p[i];
        c += g_ce2p[i];
    }
    s1[threadIdx.x] = a;
    s2[threadIdx.x] = c;
    __syncthreads();
    for (int o = 128; o > 0; o >>= 1) {
        if (threadIdx.x < (unsigned)o) {
            s1[threadIdx.x] += s1[threadIdx.x + o];
            s2[threadIdx.x] += s2[threadIdx.x + o];
        }
        __syncthreads();
    }
    if (threadIdx.x == 0)
        out[pen_idx] = s1[0] / (float)B_ + s2[0] / (2.f * (float)B_);
}

// ---------------------------------------------------------------------------
extern "C" void kernel_launch(void* const* d_in, const int* in_sizes, int n_in,
                              void* d_out, int out_size)
{
    const float* x  = nullptr;
    const int*   lb = nullptr;
    const float* W1 = nullptr;
    const float* b1 = nullptr;
    const float* W2 = nullptr;
    const float* b2 = nullptr;

    for (int i = 0; i < n_in; i++) {
        switch (in_sizes[i]) {
            case B_ * D_:         x  = (const float*)d_in[i]; break;
            case B_:              lb = (const int*)  d_in[i]; break;
            case N1_ * D_:        W1 = (const float*)d_in[i]; break;
            case N1_:             b1 = (const float*)d_in[i]; break;
            case F1_ * N1_ * D_:  W2 = (const float*)d_in[i]; break;
            case F1_ * N1_:       b2 = (const float*)d_in[i]; break;
            default: break;
        }
    }

    float* out = (float*)d_out;

    cudaFuncSetAttribute(gemm_mma, cudaFuncAttributeMaxDynamicSharedMemorySize, SMEM_DYN);

    conv_x_k<<<2048, 256>>>(x);
    conv_w_k<<<512, 256>>>(W2, W1, b2, b1);
    gemm_mma<<<dim3(9, 128), 256, SMEM_DYN>>>(out);
    penalty_ce<<<B_ / 8, 256>>>(lb, out);
    if (out_size > (long long)B_ * NOUT_)
        finalize_penalty<<<1, 256>>>(out, (long long)B_ * NOUT_);
}

// round 11
// speedup vs baseline: 1.2875x; 1.2875x over previous
#include <cuda_runtime.h>
#include <cuda_fp16.h>
#include <math.h>
#include <stdint.h>

#define B_    16384
#define D_    2048
#define F1_   32
#define N1_   33
#define N2_   1056       // F1*(F2+1)
#define NCAT_ 1089       // N2_ + N1_
#define NPAD_ 1152       // padded to 9*128
#define NOUT_ 1024

// ---------------- scratch (device globals; allocation-free) ----------------
__device__ __half g_xhi[(size_t)B_ * D_];
__device__ __half g_xlo[(size_t)B_ * D_];
__device__ __half g_wh [(size_t)NPAD_ * D_];
__device__ float g_bias[NPAD_];
__device__ float g_col0[(size_t)B_ * F1_];   // logits2[:, :, 0]
__device__ float g_l1[(size_t)B_ * N1_];
__device__ float g_ce1p[B_];
__device__ float g_ce2p[B_];

// ---------------- PTX helpers (sm_80+ only) ----------------
__device__ __forceinline__ uint32_t smem_u32(const void* p) {
    uint32_t a;
    asm("{ .reg .u64 t; cvta.to.shared.u64 t, %1; cvt.u32.u64 %0, t; }"
        : "=r"(a) : "l"(p));
    return a;
}
__device__ __forceinline__ void cpasync16(uint32_t dst, const void* src) {
    asm volatile("cp.async.cg.shared.global [%0], [%1], 16;"
                 :: "r"(dst), "l"(src) : "memory");
}
#define CP_COMMIT() asm volatile("cp.async.commit_group;" ::: "memory")

#define SW128(o) ((o) ^ (((o) >> 3) & 0x70))

__device__ __forceinline__ void ldsm_x4(uint32_t* r, uint32_t addr) {
    asm volatile("ldmatrix.sync.aligned.m8n8.x4.shared.b16 {%0,%1,%2,%3}, [%4];"
                 : "=r"(r[0]), "=r"(r[1]), "=r"(r[2]), "=r"(r[3]) : "r"(addr));
}
__device__ __forceinline__ void ldsm_x2(uint32_t* r, uint32_t addr) {
    asm volatile("ldmatrix.sync.aligned.m8n8.x2.shared.b16 {%0,%1}, [%2];"
                 : "=r"(r[0]), "=r"(r[1]) : "r"(addr));
}
__device__ __forceinline__ void mma_f16(float* d, const uint32_t* a, const uint32_t* b) {
    asm volatile(
        "mma.sync.aligned.m16n8k16.row.col.f32.f16.f16.f32 "
        "{%0,%1,%2,%3}, {%4,%5,%6,%7}, {%8,%9}, {%0,%1,%2,%3};"
        : "+f"(d[0]), "+f"(d[1]), "+f"(d[2]), "+f"(d[3])
        : "r"(a[0]), "r"(a[1]), "r"(a[2]), "r"(a[3]), "r"(b[0]), "r"(b[1]));
}

// ---------------- conversion kernels ----------------
__global__ __launch_bounds__(256)
void conv_x_k(const float* __restrict__ x)
{
    const size_t n4 = (size_t)B_ * D_ / 4;
    __half2* hi2 = reinterpret_cast<__half2*>(g_xhi);
    __half2* lo2 = reinterpret_cast<__half2*>(g_xlo);
    for (size_t i = (size_t)blockIdx.x * blockDim.x + threadIdx.x; i < n4;
         i += (size_t)gridDim.x * blockDim.x) {
        float4 v = reinterpret_cast<const float4*>(x)[i];
        __half h0 = __float2half(v.x);
        __half h1 = __float2half(v.y);
        __half h2 = __float2half(v.z);
        __half h3 = __float2half(v.w);
        __half l0 = __float2half(v.x - __half2float(h0));
        __half l1 = __float2half(v.y - __half2float(h1));
        __half l2 = __float2half(v.z - __half2float(h2));
        __half l3 = __float2half(v.w - __half2float(h3));
        __half2 a, b, c, d;
        a.x = h0; a.y = h1; b.x = h2; b.y = h3;
        c.x = l0; c.y = l1; d.x = l2; d.y = l3;
        hi2[i * 2] = a; hi2[i * 2 + 1] = b;
        lo2[i * 2] = c; lo2[i * 2 + 1] = d;
    }
}

__global__ __launch_bounds__(256)
void conv_w_k(const float* __restrict__ W2, const float* __restrict__ W1,
              const float* __restrict__ b2, const float* __restrict__ b1)
{
    const size_t n4 = (size_t)NPAD_ * D_ / 4;
    __half2* wh2 = reinterpret_cast<__half2*>(g_wh);
    size_t tid0 = (size_t)blockIdx.x * blockDim.x + threadIdx.x;
    for (size_t i = tid0; i < n4; i += (size_t)gridDim.x * blockDim.x) {
        size_t row = i >> 9;
        size_t inr = i & 511;
        float4 v = make_float4(0.f, 0.f, 0.f, 0.f);
        if (row < N2_)
            v = reinterpret_cast<const float4*>(W2)[row * 512 + inr];
        else if (row < NCAT_)
            v = reinterpret_cast<const float4*>(W1)[(row - N2_) * 512 + inr];
        __half2 a, b;
        a.x = __float2half(v.x); a.y = __float2half(v.y);
        b.x = __float2half(v.z); b.y = __float2half(v.w);
        wh2[i * 2] = a; wh2[i * 2 + 1] = b;
    }
    if (tid0 < NPAD_) {
        float bv = 0.f;
        if (tid0 < N2_)        bv = b2[tid0];
        else if (tid0 < NCAT_) bv = b1[tid0 - N2_];
        g_bias[tid0] = bv;
    }
}

// ---------------- warp-MMA GEMM + fused scatter epilogue ----------------
// grid (9, 128); BM=BN=128, BK=64; 8 warps, warp tile 64x32.
// fp16 split: logits = (xh + xl) @ wh^T ; 2 MMA passes per k16.
#define KTILES 32
#define STAGE_BYTES 49152   // Ah(16K) | Al(16K) | Bh(16K)
#define SMEM_DYN (3 * STAGE_BYTES + 1024)

__global__ __launch_bounds__(256, 1)
void gemm_mma(float* __restrict__ out)
{
    extern __shared__ char dyn[];
    const uint32_t base = (smem_u32(dyn) + 1023u) & ~1023u;

    const int tid = threadIdx.x;
    const int wid = tid >> 5;
    const int lid = tid & 31;
    const int bn = blockIdx.x * 128;
    const int bm = blockIdx.y * 128;

    const int wm = (wid & 1) * 64;
    const int wn = (wid >> 1) * 32;

    float acc[4][4][4];
#pragma unroll
    for (int i = 0; i < 4; i++)
#pragma unroll
        for (int j = 0; j < 4; j++)
#pragma unroll
            for (int k = 0; k < 4; k++) acc[i][j][k] = 0.f;

    auto load_tile = [&](int kt) {
        const uint32_t sb = base + (kt % 3) * STAGE_BYTES;
        const int kelt = kt * 64;
#pragma unroll
        for (int q = 0; q < 4; q++) {
            int id  = q * 256 + tid;
            int row = id >> 3;
            int c   = id & 7;
            uint32_t off = SW128((uint32_t)(row * 128 + c * 16));
            size_t aoff = (size_t)(bm + row) * D_ + kelt + c * 8;
            size_t boff = (size_t)(bn + row) * D_ + kelt + c * 8;
            cpasync16(sb + 0     + off, g_xhi + aoff);
            cpasync16(sb + 16384 + off, g_xlo + aoff);
            cpasync16(sb + 32768 + off, g_wh  + boff);
        }
    };

    load_tile(0); CP_COMMIT();
    load_tile(1); CP_COMMIT();

    const int a_r  = ((lid >> 3) & 1) * 8 + (lid & 7);
    const int a_kb = ((lid >> 4) & 1) * 8;
    const int b_r  = lid & 7;
    const int b_kb = ((lid >> 3) & 1) * 8;

    for (int kt = 0; kt < KTILES; kt++) {
        if (kt + 1 < KTILES) asm volatile("cp.async.wait_group 1;" ::: "memory");
        else                 asm volatile("cp.async.wait_group 0;" ::: "memory");
        __syncthreads();

        if (kt + 2 < KTILES) { load_tile(kt + 2); CP_COMMIT(); }

        const uint32_t sb  = base + (kt % 3) * STAGE_BYTES;
        const uint32_t sAh = sb;
        const uint32_t sAl = sb + 16384;
        const uint32_t sBh = sb + 32768;

#pragma unroll
        for (int k16 = 0; k16 < 4; k16++) {
            const int kb = k16 * 16;
            uint32_t ah[4][4], al[4][4], bh[4][2];
#pragma unroll
            for (int mf = 0; mf < 4; mf++) {
                uint32_t off = (uint32_t)((wm + mf * 16 + a_r) * 128 + (kb + a_kb) * 2);
                uint32_t sw = SW128(off);
                ldsm_x4(ah[mf], sAh + sw);
                ldsm_x4(al[mf], sAl + sw);
            }
#pragma unroll
            for (int nf = 0; nf < 4; nf++) {
                uint32_t off = (uint32_t)((wn + nf * 8 + b_r) * 128 + (kb + b_kb) * 2);
                uint32_t sw = SW128(off);
                ldsm_x2(bh[nf], sBh + sw);
            }
            // pass 1: xh * wh
#pragma unroll
            for (int mf = 0; mf < 4; mf++)
#pragma unroll
                for (int nf = 0; nf < 4; nf++)
                    mma_f16(acc[mf][nf], ah[mf], bh[nf]);
            // pass 2: xl * wh
#pragma unroll
            for (int mf = 0; mf < 4; mf++)
#pragma unroll
                for (int nf = 0; nf < 4; nf++)
                    mma_f16(acc[mf][nf], al[mf], bh[nf]);
        }
    }

    // ---- fused scatter epilogue ----
    const int lrow = lid >> 2;
    const int lcol = (lid & 3) * 2;

#pragma unroll
    for (int mf = 0; mf < 4; mf++)
#pragma unroll
        for (int nf = 0; nf < 4; nf++) {
            int r0 = bm + wm + mf * 16 + lrow;
            int c0 = bn + wn + nf * 8 + lcol;
            float* d = acc[mf][nf];
#pragma unroll
            for (int e = 0; e < 4; e++) {
                int rr = r0 + (e >> 1) * 8;
                int cc = c0 + (e & 1);
                float v = d[e] + g_bias[cc];
                if (cc < N2_) {
                    int j = cc / 33;
                    int k = cc - j * 33;
                    if (k > 0)
                        out[(size_t)rr * NOUT_ + j * 32 + (k - 1)] = v;
                    else
                        g_col0[(size_t)rr * F1_ + j] = v;
                } else if (cc < NCAT_) {
                    g_l1[(size_t)rr * N1_ + (cc - N2_)] = v;
                }
            }
        }
}

// ---------------- warp-per-row CE penalty kernel ----------------
__global__ __launch_bounds__(256)
void penalty_ce(const int* __restrict__ labels, const float* __restrict__ out)
{
    const int wid = threadIdx.x >> 5;
    const int j   = threadIdx.x & 31;
    const int b   = blockIdx.x * 8 + wid;

    const int lab = labels[b];
    const int g = lab >> 5;
    const int w = lab & 31;

    const float* rowp = out + (size_t)b * NOUT_ + j * 32;
    float p[32];
#pragma unroll
    for (int q = 0; q < 8; q++) {
        float4 v = *reinterpret_cast<const float4*>(rowp + q * 4);
        p[q * 4 + 0] = v.x; p[q * 4 + 1] = v.y;
        p[q * 4 + 2] = v.z; p[q * 4 + 3] = v.w;
    }
    float p0 = g_col0[(size_t)b * F1_ + j];

    float m = p0;
#pragma unroll
    for (int k = 0; k < 32; k++) m = fmaxf(m, p[k]);
    float s = expf(p0 - m);
#pragma unroll
    for (int k = 0; k < 32; k++) s += expf(p[k] - m);
    float lse = m + logf(s);
    float tgt = (j == g) ? p[w] : p0;
    float v = lse - tgt;
#pragma unroll
    for (int o = 16; o > 0; o >>= 1)
        v += __shfl_down_sync(0xffffffffu, v, o);

    const float* l1p = g_l1 + (size_t)b * N1_;
    float q1 = l1p[j];
    float q2 = (j == 0) ? l1p[32] : -1e30f;
    float mm = fmaxf(q1, q2);
#pragma unroll
    for (int o = 16; o > 0; o >>= 1)
        mm = fmaxf(mm, __shfl_xor_sync(0xffffffffu, mm, o));
    float ss = expf(q1 - mm) + ((j == 0) ? expf(q2 - mm) : 0.f);
#pragma unroll
    for (int o = 16; o > 0; o >>= 1)
        ss += __shfl_xor_sync(0xffffffffu, ss, o);
    if (j == 0) {
        g_ce2p[b] = v;
        float tgt1 = l1p[g + 1];
        g_ce1p[b] = mm + logf(ss) - tgt1;
    }
}

__global__ __launch_bounds__(256)
void finalize_penalty(float* __restrict__ out, long long pen_idx)
{
    __shared__ float s1[256];
    __shared__ float s2[256];
    float a = 0.f, c = 0.f;
    for (int i = threadIdx.x; i < B_; i += 256) {
        a += g_ce1p[i];
        c += g_ce2p[i];
    }
    s1[threadIdx.x] = a;
    s2[threadIdx.x] = c;
    __syncthreads();
    for (int o = 128; o > 0; o >>= 1) {
        if (threadIdx.x < (unsigned)o) {
            s1[threadIdx.x] += s1[threadIdx.x + o];
            s2[threadIdx.x] += s2[threadIdx.x + o];
        }
        __syncthreads();
    }
    if (threadIdx.x == 0)
        out[pen_idx] = s1[0] / (float)B_ + s2[0] / (2.f * (float)B_);
}

// ---------------------------------------------------------------------------
extern "C" void kernel_launch(void* const* d_in, const int* in_sizes, int n_in,
                              void* d_out, int out_size)
{
    const float* x  = nullptr;
    const int*   lb = nullptr;
    const float* W1 = nullptr;
    const float* b1 = nullptr;
    const float* W2 = nullptr;
    const float* b2 = nullptr;

    for (int i = 0; i < n_in; i++) {
        switch (in_sizes[i]) {
            case B_ * D_:         x  = (const float*)d_in[i]; break;
            case B_:              lb = (const int*)  d_in[i]; break;
            case N1_ * D_:        W1 = (const float*)d_in[i]; break;
            case N1_:             b1 = (const float*)d_in[i]; break;
            case F1_ * N1_ * D_:  W2 = (const float*)d_in[i]; break;
            case F1_ * N1_:       b2 = (const float*)d_in[i]; break;
            default: break;
        }
    }

    float* out = (float*)d_out;

    cudaFuncSetAttribute(gemm_mma, cudaFuncAttributeMaxDynamicSharedMemorySize, SMEM_DYN);

    conv_x_k<<<2048, 256>>>(x);
    conv_w_k<<<512, 256>>>(W2, W1, b2, b1);
    gemm_mma<<<dim3(9, 128), 256, SMEM_DYN>>>(out);
    penalty_ce<<<B_ / 8, 256>>>(lb, out);
    if (out_size > (long long)B_ * NOUT_)
        finalize_penalty<<<1, 256>>>(out, (long long)B_ * NOUT_);
}

// round 12
// speedup vs baseline: 1.9360x; 1.5037x over previous
#include <cuda_runtime.h>
#include <cuda_fp16.h>
#include <math.h>
#include <stdint.h>

#define B_    16384
#define D_    2048
#define F1_   32
#define N1_   33
#define N2_   1056       // F1*(F2+1)
#define NCAT_ 1089       // N2_ + N1_
#define NPAD_ 1152       // padded to 9*128
#define NOUT_ 1024

// ---------------- scratch (device globals; allocation-free) ----------------
__device__ __half g_xh[(size_t)B_ * D_];
__device__ __half g_wh[(size_t)NPAD_ * D_];
__device__ float g_bias[NPAD_];
__device__ float g_col0[(size_t)B_ * F1_];   // logits2[:, :, 0]
__device__ float g_l1[(size_t)B_ * N1_];
__device__ float g_ce1p[B_];
__device__ float g_ce2p[B_];

// ---------------- PTX helpers (sm_80+ only) ----------------
__device__ __forceinline__ uint32_t smem_u32(const void* p) {
    uint32_t a;
    asm("{ .reg .u64 t; cvta.to.shared.u64 t, %1; cvt.u32.u64 %0, t; }"
        : "=r"(a) : "l"(p));
    return a;
}
__device__ __forceinline__ void cpasync16(uint32_t dst, const void* src) {
    asm volatile("cp.async.cg.shared.global [%0], [%1], 16;"
                 :: "r"(dst), "l"(src) : "memory");
}
#define CP_COMMIT() asm volatile("cp.async.commit_group;" ::: "memory")

#define SW128(o) ((o) ^ (((o) >> 3) & 0x70))

__device__ __forceinline__ void ldsm_x4(uint32_t* r, uint32_t addr) {
    asm volatile("ldmatrix.sync.aligned.m8n8.x4.shared.b16 {%0,%1,%2,%3}, [%4];"
                 : "=r"(r[0]), "=r"(r[1]), "=r"(r[2]), "=r"(r[3]) : "r"(addr));
}
__device__ __forceinline__ void mma_f16(float* d, const uint32_t* a, const uint32_t* b) {
    asm volatile(
        "mma.sync.aligned.m16n8k16.row.col.f32.f16.f16.f32 "
        "{%0,%1,%2,%3}, {%4,%5,%6,%7}, {%8,%9}, {%0,%1,%2,%3};"
        : "+f"(d[0]), "+f"(d[1]), "+f"(d[2]), "+f"(d[3])
        : "r"(a[0]), "r"(a[1]), "r"(a[2]), "r"(a[3]), "r"(b[0]), "r"(b[1]));
}

// ---------------- conversion kernels ----------------
__global__ __launch_bounds__(256)
void conv_x_k(const float* __restrict__ x)
{
    const size_t n4 = (size_t)B_ * D_ / 4;
    __half2* h2 = reinterpret_cast<__half2*>(g_xh);
    for (size_t i = (size_t)blockIdx.x * blockDim.x + threadIdx.x; i < n4;
         i += (size_t)gridDim.x * blockDim.x) {
        float4 v = reinterpret_cast<const float4*>(x)[i];
        __half2 a, b;
        a.x = __float2half(v.x); a.y = __float2half(v.y);
        b.x = __float2half(v.z); b.y = __float2half(v.w);
        h2[i * 2] = a; h2[i * 2 + 1] = b;
    }
}

__global__ __launch_bounds__(256)
void conv_w_k(const float* __restrict__ W2, const float* __restrict__ W1,
              const float* __restrict__ b2, const float* __restrict__ b1)
{
    const size_t n4 = (size_t)NPAD_ * D_ / 4;
    __half2* wh2 = reinterpret_cast<__half2*>(g_wh);
    size_t tid0 = (size_t)blockIdx.x * blockDim.x + threadIdx.x;
    for (size_t i = tid0; i < n4; i += (size_t)gridDim.x * blockDim.x) {
        size_t row = i >> 9;
        size_t inr = i & 511;
        float4 v = make_float4(0.f, 0.f, 0.f, 0.f);
        if (row < N2_)
            v = reinterpret_cast<const float4*>(W2)[row * 512 + inr];
        else if (row < NCAT_)
            v = reinterpret_cast<const float4*>(W1)[(row - N2_) * 512 + inr];
        __half2 a, b;
        a.x = __float2half(v.x); a.y = __float2half(v.y);
        b.x = __float2half(v.z); b.y = __float2half(v.w);
        wh2[i * 2] = a; wh2[i * 2 + 1] = b;
    }
    if (tid0 < NPAD_) {
        float bv = 0.f;
        if (tid0 < N2_)        bv = b2[tid0];
        else if (tid0 < NCAT_) bv = b1[tid0 - N2_];
        g_bias[tid0] = bv;
    }
}

// ---------------- warp-MMA GEMM + fused scatter epilogue ----------------
// grid (9, 128); BM=BN=128, BK=64; 8 warps, warp tile 64x32.
// Single fp16 product: logits = fp16(x) @ fp16(w)^T ; 16 MMAs per k16.
// B fragments packed two-per-ldmatrix.x4 (lanes 0-15 nf, 16-31 nf+1).
#define KTILES 32
#define STAGE_BYTES 32768   // Ah(16K) | Bh(16K)
#define SMEM_DYN (3 * STAGE_BYTES + 1024)

__global__ __launch_bounds__(256, 1)
void gemm_mma(float* __restrict__ out)
{
    extern __shared__ char dyn[];
    const uint32_t base = (smem_u32(dyn) + 1023u) & ~1023u;

    const int tid = threadIdx.x;
    const int wid = tid >> 5;
    const int lid = tid & 31;
    const int bn = blockIdx.x * 128;
    const int bm = blockIdx.y * 128;

    const int wm = (wid & 1) * 64;
    const int wn = (wid >> 1) * 32;

    float acc[4][4][4];
#pragma unroll
    for (int i = 0; i < 4; i++)
#pragma unroll
        for (int j = 0; j < 4; j++)
#pragma unroll
            for (int k = 0; k < 4; k++) acc[i][j][k] = 0.f;

    auto load_tile = [&](int kt) {
        const uint32_t sb = base + (kt % 3) * STAGE_BYTES;
        const int kelt = kt * 64;
#pragma unroll
        for (int q = 0; q < 4; q++) {
            int id  = q * 256 + tid;
            int row = id >> 3;
            int c   = id & 7;
            uint32_t off = SW128((uint32_t)(row * 128 + c * 16));
            size_t aoff = (size_t)(bm + row) * D_ + kelt + c * 8;
            size_t boff = (size_t)(bn + row) * D_ + kelt + c * 8;
            cpasync16(sb + 0     + off, g_xh + aoff);
            cpasync16(sb + 16384 + off, g_wh + boff);
        }
    };

    load_tile(0); CP_COMMIT();
    load_tile(1); CP_COMMIT();

    // A ldmatrix lane map (x4: 16 rows x 16 k)
    const int a_r  = ((lid >> 3) & 1) * 8 + (lid & 7);
    const int a_kb = ((lid >> 4) & 1) * 8;
    // B ldmatrix lane map (x4 packs two 8-row n-fragments):
    //   lanes 0-7:  nf rows,  khalf0 ; lanes 8-15: nf rows,  khalf1
    //   lanes 16-23: nf+1 rows, khalf0 ; lanes 24-31: nf+1 rows, khalf1
    const int b_r4 = ((lid >> 4) & 1) * 8 + (lid & 7);
    const int b_k4 = ((lid >> 3) & 1) * 8;

    for (int kt = 0; kt < KTILES; kt++) {
        if (kt + 1 < KTILES) asm volatile("cp.async.wait_group 1;" ::: "memory");
        else                 asm volatile("cp.async.wait_group 0;" ::: "memory");
        __syncthreads();

        if (kt + 2 < KTILES) { load_tile(kt + 2); CP_COMMIT(); }

        const uint32_t sb  = base + (kt % 3) * STAGE_BYTES;
        const uint32_t sAh = sb;
        const uint32_t sBh = sb + 16384;

#pragma unroll
        for (int k16 = 0; k16 < 4; k16++) {
            const int kb = k16 * 16;
            uint32_t ah[4][4], bh[4][2];
#pragma unroll
            for (int mf = 0; mf < 4; mf++) {
                uint32_t off = (uint32_t)((wm + mf * 16 + a_r) * 128 + (kb + a_kb) * 2);
                ldsm_x4(ah[mf], sAh + SW128(off));
            }
#pragma unroll
            for (int np = 0; np < 2; np++) {
                uint32_t off = (uint32_t)((wn + np * 16 + b_r4) * 128 + (kb + b_k4) * 2);
                uint32_t b4[4];
                ldsm_x4(b4, sBh + SW128(off));
                bh[np * 2 + 0][0] = b4[0]; bh[np * 2 + 0][1] = b4[1];
                bh[np * 2 + 1][0] = b4[2]; bh[np * 2 + 1][1] = b4[3];
            }
#pragma unroll
            for (int mf = 0; mf < 4; mf++)
#pragma unroll
                for (int nf = 0; nf < 4; nf++)
                    mma_f16(acc[mf][nf], ah[mf], bh[nf]);
        }
    }

    // ---- fused scatter epilogue ----
    const int lrow = lid >> 2;
    const int lcol = (lid & 3) * 2;

#pragma unroll
    for (int mf = 0; mf < 4; mf++)
#pragma unroll
        for (int nf = 0; nf < 4; nf++) {
            int r0 = bm + wm + mf * 16 + lrow;
            int c0 = bn + wn + nf * 8 + lcol;
            float* d = acc[mf][nf];
#pragma unroll
            for (int e = 0; e < 4; e++) {
                int rr = r0 + (e >> 1) * 8;
                int cc = c0 + (e & 1);
                float v = d[e] + g_bias[cc];
                if (cc < N2_) {
                    int j = cc / 33;
                    int k = cc - j * 33;
                    if (k > 0)
                        out[(size_t)rr * NOUT_ + j * 32 + (k - 1)] = v;
                    else
                        g_col0[(size_t)rr * F1_ + j] = v;
                } else if (cc < NCAT_) {
                    g_l1[(size_t)rr * N1_ + (cc - N2_)] = v;
                }
            }
        }
}

// ---------------- warp-per-row CE penalty kernel ----------------
__global__ __launch_bounds__(256)
void penalty_ce(const int* __restrict__ labels, const float* __restrict__ out)
{
    const int wid = threadIdx.x >> 5;
    const int j   = threadIdx.x & 31;
    const int b   = blockIdx.x * 8 + wid;

    const int lab = labels[b];
    const int g = lab >> 5;
    const int w = lab & 31;

    const float* rowp = out + (size_t)b * NOUT_ + j * 32;
    float p[32];
#pragma unroll
    for (int q = 0; q < 8; q++) {
        float4 v = *reinterpret_cast<const float4*>(rowp + q * 4);
        p[q * 4 + 0] = v.x; p[q * 4 + 1] = v.y;
        p[q * 4 + 2] = v.z; p[q * 4 + 3] = v.w;
    }
    float p0 = g_col0[(size_t)b * F1_ + j];

    float m = p0;
#pragma unroll
    for (int k = 0; k < 32; k++) m = fmaxf(m, p[k]);
    float s = expf(p0 - m);
#pragma unroll
    for (int k = 0; k < 32; k++) s += expf(p[k] - m);
    float lse = m + logf(s);
    float tgt = (j == g) ? p[w] : p0;
    float v = lse - tgt;
#pragma unroll
    for (int o = 16; o > 0; o >>= 1)
        v += __shfl_down_sync(0xffffffffu, v, o);

    const float* l1p = g_l1 + (size_t)b * N1_;
    float q1 = l1p[j];
    float q2 = (j == 0) ? l1p[32] : -1e30f;
    float mm = fmaxf(q1, q2);
#pragma unroll
    for (int o = 16; o > 0; o >>= 1)
        mm = fmaxf(mm, __shfl_xor_sync(0xffffffffu, mm, o));
    float ss = expf(q1 - mm) + ((j == 0) ? expf(q2 - mm) : 0.f);
#pragma unroll
    for (int o = 16; o > 0; o >>= 1)
        ss += __shfl_xor_sync(0xffffffffu, ss, o);
    if (j == 0) {
        g_ce2p[b] = v;
        float tgt1 = l1p[g + 1];
        g_ce1p[b] = mm + logf(ss) - tgt1;
    }
}

__global__ __launch_bounds__(256)
void finalize_penalty(float* __restrict__ out, long long pen_idx)
{
    __shared__ float s1[256];
    __shared__ float s2[256];
    float a = 0.f, c = 0.f;
    for (int i = threadIdx.x; i < B_; i += 256) {
        a += g_ce1p[i];
        c += g_ce2p[i];
    }
    s1[threadIdx.x] = a;
    s2[threadIdx.x] = c;
    __syncthreads();
    for (int o = 128; o > 0; o >>= 1) {
        if (threadIdx.x < (unsigned)o) {
            s1[threadIdx.x] += s1[threadIdx.x + o];
            s2[threadIdx.x] += s2[threadIdx.x + o];
        }
        __syncthreads();
    }
    if (threadIdx.x == 0)
        out[pen_idx] = s1[0] / (float)B_ + s2[0] / (2.f * (float)B_);
}

// ---------------------------------------------------------------------------
extern "C" void kernel_launch(void* const* d_in, const int* in_sizes, int n_in,
                              void* d_out, int out_size)
{
    const float* x  = nullptr;
    const int*   lb = nullptr;
    const float* W1 = nullptr;
    const float* b1 = nullptr;
    const float* W2 = nullptr;
    const float* b2 = nullptr;

    for (int i = 0; i < n_in; i++) {
        switch (in_sizes[i]) {
            case B_ * D_:         x  = (const float*)d_in[i]; break;
            case B_:              lb = (const int*)  d_in[i]; break;
            case N1_ * D_:        W1 = (const float*)d_in[i]; break;
            case N1_:             b1 = (const float*)d_in[i]; break;
            case F1_ * N1_ * D_:  W2 = (const float*)d_in[i]; break;
            case F1_ * N1_:       b2 = (const float*)d_in[i]; break;
            default: break;
        }
    }

    float* out = (float*)d_out;

    cudaFuncSetAttribute(gemm_mma, cudaFuncAttributeMaxDynamicSharedMemorySize, SMEM_DYN);

    conv_x_k<<<2048, 256>>>(x);
    conv_w_k<<<512, 256>>>(W2, W1, b2, b1);
    gemm_mma<<<dim3(9, 128), 256, SMEM_DYN>>>(out);
    penalty_ce<<<B_ / 8, 256>>>(lb, out);
    if (out_size > (long long)B_ * NOUT_)
        finalize_penalty<<<1, 256>>>(out, (long long)B_ * NOUT_);
}